// round 12
// baseline (speedup 1.0000x reference)
#include <cuda_runtime.h>
#include <math.h>
#include <stdint.h>

#define BB   32
#define NN   100
#define HH   128
#define BIN  16
#define EE   20000

// Scratch (allocation-free rule: __device__ globals)
__device__ float d_P[BB * NN * HH];    // P[b,n,k] = lf[b,n]·W_apair[:,k] + 0.5*b_binary[k]
__device__ float d_G[BB * NN * HH];    // global_feats
__device__ float d_ATT[BB * NN * NN];  // att_score[b,i,j]

// ---- tf32 helpers ---------------------------------------------------------
__device__ __forceinline__ uint32_t tf32b(float x) {
    uint32_t r; asm("cvt.rna.tf32.f32 %0, %1;" : "=r"(r) : "f"(x)); return r;
}
__device__ __forceinline__ void mma_tf32(float* d, const uint32_t* a, const uint32_t* bq) {
    asm volatile("mma.sync.aligned.m16n8k8.row.col.f32.tf32.tf32.f32 "
                 "{%0,%1,%2,%3}, {%4,%5,%6,%7}, {%8,%9}, {%0,%1,%2,%3};"
                 : "+f"(d[0]), "+f"(d[1]), "+f"(d[2]), "+f"(d[3])
                 : "r"(a[0]), "r"(a[1]), "r"(a[2]), "r"(a[3]),
                   "r"(bq[0]), "r"(bq[1]));
}

// ---------------------------------------------------------------------------
// Kernel A: P = lf·Wap + 0.5*bb. RA=8 rows/block, 4-way split-K, block 512.
// ---------------------------------------------------------------------------
#define RA 8
__global__ __launch_bounds__(512) void kA(const float* __restrict__ lf,
                                          const float* __restrict__ Wap,
                                          const float* __restrict__ bb) {
    const int r0  = blockIdx.x * RA;
    const int tid = threadIdx.x;
    const int k   = tid & (HH - 1);
    const int q   = tid >> 7;

    __shared__ float row[RA][HH];
    __shared__ float part[4][RA][HH];

    if (tid < RA * HH / 4) {
        const float4* lsrc = (const float4*)(lf + (size_t)r0 * HH);
        ((float4*)row)[tid] = lsrc[tid];
    }
    __syncthreads();

    float acc[RA];
    const float binit = (q == 0) ? 0.5f * bb[k] : 0.f;
    #pragma unroll
    for (int r = 0; r < RA; ++r) acc[r] = binit;

    const int h0 = q * 32;
    #pragma unroll 8
    for (int h = h0; h < h0 + 32; ++h) {
        const float wv = Wap[h * HH + k];
        #pragma unroll
        for (int r = 0; r < RA; ++r)
            acc[r] = fmaf(row[r][h], wv, acc[r]);
    }
    #pragma unroll
    for (int r = 0; r < RA; ++r) part[q][r][k] = acc[r];
    __syncthreads();

    for (int t = tid; t < RA * HH; t += 512) {
        const int r = t >> 7, kk = t & (HH - 1);
        d_P[(size_t)(r0 + r) * HH + kk] =
            (part[0][r][kk] + part[1][r][kk]) + (part[2][r][kk] + part[3][r][kk]);
    }
}

// ---------------------------------------------------------------------------
// Kernel B1m: att_score via tf32 mma.sync.
// Block = (b, 2-i tile), 512 threads = 16 warps: warp = (i_local, ch).
// Each warp owns ONE 16-wide k-chunk -> ~48 live regs, no spill at (512,2).
// 8 ch partials combined via red + fused sigmoid.
// ---------------------------------------------------------------------------
#define TIM 2
#define PS  132   // P_sh row stride
#define BSX 20    // bin_s row stride: conflict-free A-frag LDS
#define WSX 136   // Wb_s row stride: conflict-free B-frag LDS
// P_sh 59136 + bin_s 2*112*20*4=17920 + Wb_s 8704 + wa 512 + red 2*8*112*4=7168
#define KB1M_SMEM (59136 + 17920 + 8704 + 512 + 7168)   // 93440 B

__global__ __launch_bounds__(512, 2) void kB1m(const float* __restrict__ bin,
                                               const float* __restrict__ Wb,
                                               const float* __restrict__ Watt,
                                               const float* __restrict__ batt) {
    extern __shared__ float smem[];
    float* P_sh  = smem;                          // [112][PS]
    float* bin_s = smem + 112 * PS;               // [TIM][112][BSX] tf32 bits
    float* Wb_s  = bin_s + TIM * 112 * BSX;       // [16][WSX]       tf32 bits
    float* wa_sh = Wb_s + 16 * WSX;               // [128]
    float* red   = wa_sh + 128;                   // [TIM][8][112]

    const int b    = blockIdx.x / (NN / TIM);
    const int i0   = (blockIdx.x % (NN / TIM)) * TIM;
    const int tid  = threadIdx.x;
    const int w    = tid >> 5;
    const int lane = tid & 31;
    const int g    = lane >> 2;   // 0..7 (row sel)
    const int tg   = lane & 3;    // 0..3 (col sel)
    const int il   = w >> 3;      // i_local 0..1
    const int ch   = w & 7;       // k-chunk 0..7

    // zero ONLY pad rows (100..111)
    for (int t = tid; t < TIM * 12 * BSX; t += 512) {
        const int ii = t / (12 * BSX);
        bin_s[(ii * 112 + 100) * BSX + (t - ii * 12 * BSX)] = 0.f;
    }
    for (int t = tid; t < 12 * PS; t += 512) P_sh[100 * PS + t] = 0.f;

    // stage P_sh rows 0..99 (fp32)
    {
        const float4* Ps = (const float4*)(d_P + (size_t)b * NN * HH);
        for (int t = tid; t < NN * 32; t += 512) {
            const int j = t >> 5, kqq = t & 31;
            ((float4*)(P_sh + j * PS))[kqq] = Ps[t];
        }
    }
    // stage bin_s (tf32)
    for (int t = tid; t < TIM * 400; t += 512) {
        const int ii  = t / 400;
        const int rem = t - ii * 400;
        const int r   = rem >> 2, q = rem & 3;
        const float4 v = __ldg((const float4*)bin +
                               ((size_t)(b * NN + i0 + ii) * NN + r) * 4 + q);
        float* ds = bin_s + (ii * 112 + r) * BSX + 4 * q;
        ds[0] = __uint_as_float(tf32b(v.x));
        ds[1] = __uint_as_float(tf32b(v.y));
        ds[2] = __uint_as_float(tf32b(v.z));
        ds[3] = __uint_as_float(tf32b(v.w));
    }
    // stage Wb_s (tf32)
    if (tid < 16 * 32) {
        const int c = tid >> 5, kqq = tid & 31;
        const float4 v = ((const float4*)Wb)[tid];
        float* ds = Wb_s + c * WSX + 4 * kqq;
        ds[0] = __uint_as_float(tf32b(v.x));
        ds[1] = __uint_as_float(tf32b(v.y));
        ds[2] = __uint_as_float(tf32b(v.z));
        ds[3] = __uint_as_float(tf32b(v.w));
    }
    if (tid < HH) wa_sh[tid] = Watt[tid];
    __syncthreads();

    const int i  = i0 + il;
    const int nb = ch * 16;
    const uint32_t* binU = (const uint32_t*)(bin_s + il * 112 * BSX);
    const uint32_t* WbU  = (const uint32_t*)Wb_s;

    // Hoisted warp-constant fragments: B, P_i, wa
    uint32_t bfr[2][2][2];   // [Kt][nt][r]
    float2   piv[2], wav[2];
    #pragma unroll
    for (int nt = 0; nt < 2; ++nt) {
        const int kf = nb + nt * 8 + g;
        bfr[0][nt][0] = WbU[(tg)      * WSX + kf];
        bfr[0][nt][1] = WbU[(tg + 4)  * WSX + kf];
        bfr[1][nt][0] = WbU[(tg + 8)  * WSX + kf];
        bfr[1][nt][1] = WbU[(tg + 12) * WSX + kf];
        piv[nt] = *(const float2*)(P_sh + i * PS + nb + nt * 8 + 2 * tg);
        wav[nt] = *(const float2*)(wa_sh + nb + nt * 8 + 2 * tg);
    }

    #pragma unroll
    for (int Mt = 0; Mt < 7; ++Mt) {
        const int r0 = Mt * 16 + g;

        uint32_t a0[4], a1[4];
        a0[0] = binU[(r0)     * BSX + tg];
        a0[1] = binU[(r0 + 8) * BSX + tg];
        a0[2] = binU[(r0)     * BSX + tg + 4];
        a0[3] = binU[(r0 + 8) * BSX + tg + 4];
        a1[0] = binU[(r0)     * BSX + tg + 8];
        a1[1] = binU[(r0 + 8) * BSX + tg + 8];
        a1[2] = binU[(r0)     * BSX + tg + 12];
        a1[3] = binU[(r0 + 8) * BSX + tg + 12];

        float acc[2][4];
        #pragma unroll
        for (int nt = 0; nt < 2; ++nt) {
            const int k0 = nb + nt * 8 + 2 * tg;
            const float2 pj0 = *(const float2*)(P_sh + (r0)     * PS + k0);
            const float2 pj1 = *(const float2*)(P_sh + (r0 + 8) * PS + k0);
            acc[nt][0] = piv[nt].x + pj0.x;
            acc[nt][1] = piv[nt].y + pj0.y;
            acc[nt][2] = piv[nt].x + pj1.x;
            acc[nt][3] = piv[nt].y + pj1.y;
        }

        mma_tf32(acc[0], a0, bfr[0][0]);
        mma_tf32(acc[0], a1, bfr[1][0]);
        mma_tf32(acc[1], a0, bfr[0][1]);
        mma_tf32(acc[1], a1, bfr[1][1]);

        float x0 = 0.f, x1 = 0.f;
        x0 = fmaf(fmaxf(acc[0][0], 0.f), wav[0].x, x0);
        x0 = fmaf(fmaxf(acc[0][1], 0.f), wav[0].y, x0);
        x0 = fmaf(fmaxf(acc[1][0], 0.f), wav[1].x, x0);
        x0 = fmaf(fmaxf(acc[1][1], 0.f), wav[1].y, x0);
        x1 = fmaf(fmaxf(acc[0][2], 0.f), wav[0].x, x1);
        x1 = fmaf(fmaxf(acc[0][3], 0.f), wav[0].y, x1);
        x1 = fmaf(fmaxf(acc[1][2], 0.f), wav[1].x, x1);
        x1 = fmaf(fmaxf(acc[1][3], 0.f), wav[1].y, x1);

        x0 += __shfl_xor_sync(0xFFFFFFFFu, x0, 1);
        x0 += __shfl_xor_sync(0xFFFFFFFFu, x0, 2);
        x1 += __shfl_xor_sync(0xFFFFFFFFu, x1, 1);
        x1 += __shfl_xor_sync(0xFFFFFFFFu, x1, 2);
        if (tg == 0) {
            red[(il * 8 + ch) * 112 + Mt * 16 + g]     = x0;
            red[(il * 8 + ch) * 112 + Mt * 16 + g + 8] = x1;
        }
    }
    __syncthreads();

    // combine 8 ch partials + sigmoid + store
    if (tid < TIM * 112) {
        const int ii = tid / 112;
        const int j  = tid - ii * 112;
        if (j < NN) {
            const float* r8 = red + ii * 8 * 112 + j;
            const float x = ((r8[0] + r8[112]) + (r8[224] + r8[336]))
                          + ((r8[448] + r8[560]) + (r8[672] + r8[784]));
            const float s = 1.f / (1.f + __expf(-(x + batt[0])));
            d_ATT[(size_t)(b * NN + i0 + ii) * NN + j] = s;
        }
    }
}

// ---------------------------------------------------------------------------
// Kernel B2: g[b,i,k] = sum_j att[b,i,j] * lf[b,j,k].
// ---------------------------------------------------------------------------
#define TI2 10
#define KB2_SMEM (NN * HH * 4 + TI2 * NN * 4)   // 55200 B

__global__ __launch_bounds__(128) void kB2(const float* __restrict__ lf) {
    extern __shared__ float sm2[];
    float* L_sh = sm2;               // [NN][HH]
    float* s_sh = sm2 + NN * HH;     // [TI2][NN]

    const int b   = blockIdx.x / (NN / TI2);
    const int i0  = (blockIdx.x % (NN / TI2)) * TI2;
    const int tid = threadIdx.x;

    {
        const float4* Ls = (const float4*)(lf + (size_t)b * NN * HH);
        float4* Ld = (float4*)L_sh;
        for (int t = tid; t < NN * HH / 4; t += 128) Ld[t] = Ls[t];
        const float* As = d_ATT + (size_t)(b * NN + i0) * NN;
        for (int t = tid; t < TI2 * NN; t += 128) s_sh[t] = As[t];
    }
    __syncthreads();

    const int k = tid;
    float acc[TI2];
    #pragma unroll
    for (int ii = 0; ii < TI2; ++ii) acc[ii] = 0.f;

    #pragma unroll 2
    for (int j = 0; j < NN; ++j) {
        const float lv = L_sh[j * HH + k];
        #pragma unroll
        for (int ii = 0; ii < TI2; ++ii)
            acc[ii] = fmaf(s_sh[ii * NN + j], lv, acc[ii]);
    }
    #pragma unroll
    for (int ii = 0; ii < TI2; ++ii)
        d_G[(size_t)(b * NN + i0 + ii) * HH + k] = acc[ii];
}

// ---------------------------------------------------------------------------
// Kernel C: gather epilogue. 8 e per 256-thread block; each thread drives
// TWO e's (MLP 4 on the gathered L2 reads). Streaming stores.
// ---------------------------------------------------------------------------
__global__ __launch_bounds__(256) void kC(const float* __restrict__ lf,
                                          const int* __restrict__ idx,
                                          float* __restrict__ out) {
    const int e0   = blockIdx.x * 8 + (threadIdx.x >> 6);
    const int e1   = e0 + 4;
    const int half = (threadIdx.x >> 5) & 1;
    const int lane = threadIdx.x & 31;

    int b0 = idx[e0 * 3 + 0], i0 = idx[e0 * 3 + 1], j0 = idx[e0 * 3 + 2];
    int b1 = idx[e1 * 3 + 0], i1 = idx[e1 * 3 + 1], j1 = idx[e1 * 3 + 2];
    b0 = min(max(b0, 0), BB - 1); i0 = min(max(i0, 0), NN - 1); j0 = min(max(j0, 0), NN - 1);
    b1 = min(max(b1, 0), BB - 1); i1 = min(max(i1, 0), NN - 1); j1 = min(max(j1, 0), NN - 1);

    const size_t ri0 = ((size_t)b0 * NN + i0) * (HH / 4);
    const size_t rj0 = ((size_t)b0 * NN + j0) * (HH / 4);
    const size_t ri1 = ((size_t)b1 * NN + i1) * (HH / 4);
    const size_t rj1 = ((size_t)b1 * NN + j1) * (HH / 4);
    float4* o = (float4*)out;

    const float4* S = (half == 0) ? (const float4*)lf : (const float4*)d_G;
    const size_t obase = (half == 0) ? 0 : (size_t)EE * 32;

    const float4 a0 = __ldg(S + ri0 + lane), c0 = __ldg(S + rj0 + lane);
    const float4 a1 = __ldg(S + ri1 + lane), c1 = __ldg(S + rj1 + lane);

    float4 r0; r0.x = a0.x + c0.x; r0.y = a0.y + c0.y; r0.z = a0.z + c0.z; r0.w = a0.w + c0.w;
    float4 r1; r1.x = a1.x + c1.x; r1.y = a1.y + c1.y; r1.z = a1.z + c1.z; r1.w = a1.w + c1.w;
    __stcs(o + obase + (size_t)e0 * 32 + lane, r0);
    __stcs(o + obase + (size_t)e1 * 32 + lane, r1);
}

// ---------------------------------------------------------------------------
extern "C" void kernel_launch(void* const* d_in, const int* in_sizes, int n_in,
                              void* d_out, int out_size) {
    const float* lf   = (const float*)d_in[0];
    const float* bin  = (const float*)d_in[1];
    const int*   sidx = (const int*)d_in[2];
    const float* Wap  = (const float*)d_in[3];
    const float* Wb   = (const float*)d_in[4];
    const float* bb   = (const float*)d_in[5];
    const float* Watt = (const float*)d_in[6];
    const float* batt = (const float*)d_in[7];
    float*       out  = (float*)d_out;

    static bool attr_set = false;
    if (!attr_set) {
        cudaFuncSetAttribute(kB1m, cudaFuncAttributeMaxDynamicSharedMemorySize, KB1M_SMEM);
        cudaFuncSetAttribute(kB2,  cudaFuncAttributeMaxDynamicSharedMemorySize, KB2_SMEM);
        attr_set = true;
    }

    kA  <<<BB * NN / RA, 512>>>(lf, Wap, bb);
    kB1m<<<BB * (NN / TIM), 512, KB1M_SMEM>>>(bin, Wb, Watt, batt);
    kB2 <<<BB * (NN / TI2), 128, KB2_SMEM>>>(lf);
    kC  <<<EE / 8, 256>>>(lf, sidx, out);
}

// round 14
// speedup vs baseline: 1.0894x; 1.0894x over previous
#include <cuda_runtime.h>
#include <math.h>
#include <stdint.h>

#define BB   32
#define NN   100
#define HH   128
#define BIN  16
#define EE   20000

// Scratch (allocation-free rule: __device__ globals)
__device__ float d_P[BB * NN * HH];    // P[b,n,k] = lf[b,n]·W_apair[:,k] + 0.5*b_binary[k]
__device__ float d_G[BB * NN * HH];    // global_feats
__device__ float d_ATT[BB * NN * NN];  // att_score[b,i,j]

// ---- tf32 helpers ---------------------------------------------------------
__device__ __forceinline__ uint32_t tf32b(float x) {
    uint32_t r; asm("cvt.rna.tf32.f32 %0, %1;" : "=r"(r) : "f"(x)); return r;
}
__device__ __forceinline__ void mma_tf32(float* d, const uint32_t* a, const uint32_t* bq) {
    asm volatile("mma.sync.aligned.m16n8k8.row.col.f32.tf32.tf32.f32 "
                 "{%0,%1,%2,%3}, {%4,%5,%6,%7}, {%8,%9}, {%0,%1,%2,%3};"
                 : "+f"(d[0]), "+f"(d[1]), "+f"(d[2]), "+f"(d[3])
                 : "r"(a[0]), "r"(a[1]), "r"(a[2]), "r"(a[3]),
                   "r"(bq[0]), "r"(bq[1]));
}

// ---------------------------------------------------------------------------
// Kernel A: P = lf·Wap + 0.5*bb. RA=8 rows/block, 4-way split-K, block 512.
// ---------------------------------------------------------------------------
#define RA 8
__global__ __launch_bounds__(512) void kA(const float* __restrict__ lf,
                                          const float* __restrict__ Wap,
                                          const float* __restrict__ bb) {
    const int r0  = blockIdx.x * RA;
    const int tid = threadIdx.x;
    const int k   = tid & (HH - 1);
    const int q   = tid >> 7;

    __shared__ float row[RA][HH];
    __shared__ float part[4][RA][HH];

    if (tid < RA * HH / 4) {
        const float4* lsrc = (const float4*)(lf + (size_t)r0 * HH);
        ((float4*)row)[tid] = lsrc[tid];
    }
    __syncthreads();

    float acc[RA];
    const float binit = (q == 0) ? 0.5f * bb[k] : 0.f;
    #pragma unroll
    for (int r = 0; r < RA; ++r) acc[r] = binit;

    const int h0 = q * 32;
    #pragma unroll 8
    for (int h = h0; h < h0 + 32; ++h) {
        const float wv = Wap[h * HH + k];
        #pragma unroll
        for (int r = 0; r < RA; ++r)
            acc[r] = fmaf(row[r][h], wv, acc[r]);
    }
    #pragma unroll
    for (int r = 0; r < RA; ++r) part[q][r][k] = acc[r];
    __syncthreads();

    for (int t = tid; t < RA * HH; t += 512) {
        const int r = t >> 7, kk = t & (HH - 1);
        d_P[(size_t)(r0 + r) * HH + kk] =
            (part[0][r][kk] + part[1][r][kk]) + (part[2][r][kk] + part[3][r][kk]);
    }
}

// ---------------------------------------------------------------------------
// Kernel B1m: att_score via tf32 mma.sync.
// Block = (b, 4-i tile), 256 threads = 8 warps: warp = (ilp in 2, kq in 4).
// Each warp processes TWO i's (ilp, ilp+2) SHARING one pj fragment load
// -> pj LDS bytes per result halved vs R11 (the LDS-BW bottleneck).
// (256,2): 128-reg budget (no spill), 2 CTAs/SM (2x111KB = 222KB smem).
// ---------------------------------------------------------------------------
#define TIM 4
#define PS  132   // P_sh row stride
#define BSX 20    // bin_s row stride: conflict-free A-frag LDS
#define WSX 136   // Wb_s row stride: conflict-free B-frag LDS
// P_sh 59136 + bin_s 4*112*20*4=35840 + Wb_s 8704 + wa 512 + red 7168
#define KB1M_SMEM (59136 + 35840 + 8704 + 512 + 7168)   // 111360 B

__global__ __launch_bounds__(256, 2) void kB1m(const float* __restrict__ bin,
                                               const float* __restrict__ Wb,
                                               const float* __restrict__ Watt,
                                               const float* __restrict__ batt) {
    extern __shared__ float smem[];
    float* P_sh  = smem;                          // [112][PS]
    float* bin_s = smem + 112 * PS;               // [TIM][112][BSX] tf32 bits
    float* Wb_s  = bin_s + TIM * 112 * BSX;       // [16][WSX]       tf32 bits
    float* wa_sh = Wb_s + 16 * WSX;               // [128]
    float* red   = wa_sh + 128;                   // [TIM][4][112]

    const int b    = blockIdx.x / (NN / TIM);
    const int i0   = (blockIdx.x % (NN / TIM)) * TIM;
    const int tid  = threadIdx.x;
    const int w    = tid >> 5;
    const int lane = tid & 31;
    const int g    = lane >> 2;   // 0..7 (row sel)
    const int tg   = lane & 3;    // 0..3 (col sel)
    const int ilp  = w >> 2;      // 0..1: i pair base
    const int kq   = w & 3;       // k-quarter

    // zero ONLY pad rows (100..111)
    for (int t = tid; t < TIM * 12 * BSX; t += 256) {
        const int ii = t / (12 * BSX);
        bin_s[(ii * 112 + 100) * BSX + (t - ii * 12 * BSX)] = 0.f;
    }
    for (int t = tid; t < 12 * PS; t += 256) P_sh[100 * PS + t] = 0.f;

    // stage P_sh rows 0..99 (fp32)
    {
        const float4* Ps = (const float4*)(d_P + (size_t)b * NN * HH);
        for (int t = tid; t < NN * 32; t += 256) {
            const int j = t >> 5, kqq = t & 31;
            ((float4*)(P_sh + j * PS))[kqq] = Ps[t];
        }
    }
    // stage bin_s (tf32)
    for (int t = tid; t < TIM * 400; t += 256) {
        const int ii  = t / 400;
        const int rem = t - ii * 400;
        const int r   = rem >> 2, q = rem & 3;
        const float4 v = __ldg((const float4*)bin +
                               ((size_t)(b * NN + i0 + ii) * NN + r) * 4 + q);
        float* ds = bin_s + (ii * 112 + r) * BSX + 4 * q;
        ds[0] = __uint_as_float(tf32b(v.x));
        ds[1] = __uint_as_float(tf32b(v.y));
        ds[2] = __uint_as_float(tf32b(v.z));
        ds[3] = __uint_as_float(tf32b(v.w));
    }
    // stage Wb_s (tf32)
    for (int t = tid; t < 16 * 32; t += 256) {
        const int c = t >> 5, kqq = t & 31;
        const float4 v = ((const float4*)Wb)[t];
        float* ds = Wb_s + c * WSX + 4 * kqq;
        ds[0] = __uint_as_float(tf32b(v.x));
        ds[1] = __uint_as_float(tf32b(v.y));
        ds[2] = __uint_as_float(tf32b(v.z));
        ds[3] = __uint_as_float(tf32b(v.w));
    }
    if (tid < HH) wa_sh[tid] = Watt[tid];
    __syncthreads();

    const int iA = i0 + ilp;        // first i
    const int iB = i0 + ilp + 2;    // second i (shares pj loads)
    const uint32_t* binA = (const uint32_t*)(bin_s + (ilp)     * 112 * BSX);
    const uint32_t* binB = (const uint32_t*)(bin_s + (ilp + 2) * 112 * BSX);
    const uint32_t* WbU  = (const uint32_t*)Wb_s;

    // Hoisted warp-constants: B frags, P_i frags (both i), wa
    uint32_t bfr[2][2][2][2];   // [cc][Kt][nt][r]
    float2   pivA[2][2], pivB[2][2], wav[2][2];   // [cc][nt]
    #pragma unroll
    for (int cc = 0; cc < 2; ++cc) {
        const int nb = (kq * 2 + cc) * 16;
        #pragma unroll
        for (int nt = 0; nt < 2; ++nt) {
            const int kf = nb + nt * 8 + g;
            bfr[cc][0][nt][0] = WbU[(tg)      * WSX + kf];
            bfr[cc][0][nt][1] = WbU[(tg + 4)  * WSX + kf];
            bfr[cc][1][nt][0] = WbU[(tg + 8)  * WSX + kf];
            bfr[cc][1][nt][1] = WbU[(tg + 12) * WSX + kf];
            const int k0 = nb + nt * 8 + 2 * tg;
            pivA[cc][nt] = *(const float2*)(P_sh + iA * PS + k0);
            pivB[cc][nt] = *(const float2*)(P_sh + iB * PS + k0);
            wav[cc][nt]  = *(const float2*)(wa_sh + k0);
        }
    }

    #pragma unroll
    for (int Mt = 0; Mt < 7; ++Mt) {
        const int r0 = Mt * 16 + g;

        // pj fragments: loaded ONCE, shared by both i's
        float2 pj[2][2][2];   // [cc][nt][rh]
        #pragma unroll
        for (int cc = 0; cc < 2; ++cc) {
            const int nb = (kq * 2 + cc) * 16;
            #pragma unroll
            for (int nt = 0; nt < 2; ++nt) {
                const int k0 = nb + nt * 8 + 2 * tg;
                pj[cc][nt][0] = *(const float2*)(P_sh + (r0)     * PS + k0);
                pj[cc][nt][1] = *(const float2*)(P_sh + (r0 + 8) * PS + k0);
            }
        }

        // ---- i = iA ----
        {
            uint32_t a0[4], a1[4];
            a0[0] = binA[(r0)     * BSX + tg];
            a0[1] = binA[(r0 + 8) * BSX + tg];
            a0[2] = binA[(r0)     * BSX + tg + 4];
            a0[3] = binA[(r0 + 8) * BSX + tg + 4];
            a1[0] = binA[(r0)     * BSX + tg + 8];
            a1[1] = binA[(r0 + 8) * BSX + tg + 8];
            a1[2] = binA[(r0)     * BSX + tg + 12];
            a1[3] = binA[(r0 + 8) * BSX + tg + 12];

            float x0 = 0.f, x1 = 0.f;
            #pragma unroll
            for (int cc = 0; cc < 2; ++cc) {
                float acc[2][4];
                #pragma unroll
                for (int nt = 0; nt < 2; ++nt) {
                    acc[nt][0] = pivA[cc][nt].x + pj[cc][nt][0].x;
                    acc[nt][1] = pivA[cc][nt].y + pj[cc][nt][0].y;
                    acc[nt][2] = pivA[cc][nt].x + pj[cc][nt][1].x;
                    acc[nt][3] = pivA[cc][nt].y + pj[cc][nt][1].y;
                }
                mma_tf32(acc[0], a0, bfr[cc][0][0]);
                mma_tf32(acc[0], a1, bfr[cc][1][0]);
                mma_tf32(acc[1], a0, bfr[cc][0][1]);
                mma_tf32(acc[1], a1, bfr[cc][1][1]);

                x0 = fmaf(fmaxf(acc[0][0], 0.f), wav[cc][0].x, x0);
                x0 = fmaf(fmaxf(acc[0][1], 0.f), wav[cc][0].y, x0);
                x0 = fmaf(fmaxf(acc[1][0], 0.f), wav[cc][1].x, x0);
                x0 = fmaf(fmaxf(acc[1][1], 0.f), wav[cc][1].y, x0);
                x1 = fmaf(fmaxf(acc[0][2], 0.f), wav[cc][0].x, x1);
                x1 = fmaf(fmaxf(acc[0][3], 0.f), wav[cc][0].y, x1);
                x1 = fmaf(fmaxf(acc[1][2], 0.f), wav[cc][1].x, x1);
                x1 = fmaf(fmaxf(acc[1][3], 0.f), wav[cc][1].y, x1);
            }
            x0 += __shfl_xor_sync(0xFFFFFFFFu, x0, 1);
            x0 += __shfl_xor_sync(0xFFFFFFFFu, x0, 2);
            x1 += __shfl_xor_sync(0xFFFFFFFFu, x1, 1);
            x1 += __shfl_xor_sync(0xFFFFFFFFu, x1, 2);
            if (tg == 0) {
                red[((ilp)     * 4 + kq) * 112 + Mt * 16 + g]     = x0;
                red[((ilp)     * 4 + kq) * 112 + Mt * 16 + g + 8] = x1;
            }
        }

        // ---- i = iB (same pj) ----
        {
            uint32_t a0[4], a1[4];
            a0[0] = binB[(r0)     * BSX + tg];
            a0[1] = binB[(r0 + 8) * BSX + tg];
            a0[2] = binB[(r0)     * BSX + tg + 4];
            a0[3] = binB[(r0 + 8) * BSX + tg + 4];
            a1[0] = binB[(r0)     * BSX + tg + 8];
            a1[1] = binB[(r0 + 8) * BSX + tg + 8];
            a1[2] = binB[(r0)     * BSX + tg + 12];
            a1[3] = binB[(r0 + 8) * BSX + tg + 12];

            float x0 = 0.f, x1 = 0.f;
            #pragma unroll
            for (int cc = 0; cc < 2; ++cc) {
                float acc[2][4];
                #pragma unroll
                for (int nt = 0; nt < 2; ++nt) {
                    acc[nt][0] = pivB[cc][nt].x + pj[cc][nt][0].x;
                    acc[nt][1] = pivB[cc][nt].y + pj[cc][nt][0].y;
                    acc[nt][2] = pivB[cc][nt].x + pj[cc][nt][1].x;
                    acc[nt][3] = pivB[cc][nt].y + pj[cc][nt][1].y;
                }
                mma_tf32(acc[0], a0, bfr[cc][0][0]);
                mma_tf32(acc[0], a1, bfr[cc][1][0]);
                mma_tf32(acc[1], a0, bfr[cc][0][1]);
                mma_tf32(acc[1], a1, bfr[cc][1][1]);

                x0 = fmaf(fmaxf(acc[0][0], 0.f), wav[cc][0].x, x0);
                x0 = fmaf(fmaxf(acc[0][1], 0.f), wav[cc][0].y, x0);
                x0 = fmaf(fmaxf(acc[1][0], 0.f), wav[cc][1].x, x0);
                x0 = fmaf(fmaxf(acc[1][1], 0.f), wav[cc][1].y, x0);
                x1 = fmaf(fmaxf(acc[0][2], 0.f), wav[cc][0].x, x1);
                x1 = fmaf(fmaxf(acc[0][3], 0.f), wav[cc][0].y, x1);
                x1 = fmaf(fmaxf(acc[1][2], 0.f), wav[cc][1].x, x1);
                x1 = fmaf(fmaxf(acc[1][3], 0.f), wav[cc][1].y, x1);
            }
            x0 += __shfl_xor_sync(0xFFFFFFFFu, x0, 1);
            x0 += __shfl_xor_sync(0xFFFFFFFFu, x0, 2);
            x1 += __shfl_xor_sync(0xFFFFFFFFu, x1, 1);
            x1 += __shfl_xor_sync(0xFFFFFFFFu, x1, 2);
            if (tg == 0) {
                red[((ilp + 2) * 4 + kq) * 112 + Mt * 16 + g]     = x0;
                red[((ilp + 2) * 4 + kq) * 112 + Mt * 16 + g + 8] = x1;
            }
        }
    }
    __syncthreads();

    // combine k-quarters + sigmoid + store
    for (int t = tid; t < TIM * 112; t += 256) {
        const int ii = t / 112;
        const int j  = t - ii * 112;
        if (j < NN) {
            const float* r4 = red + ii * 4 * 112 + j;
            const float x = (r4[0] + r4[112]) + (r4[224] + r4[336]);
            const float s = 1.f / (1.f + __expf(-(x + batt[0])));
            d_ATT[(size_t)(b * NN + i0 + ii) * NN + j] = s;
        }
    }
}

// ---------------------------------------------------------------------------
// Kernel B2: g[b,i,k] = sum_j att[b,i,j] * lf[b,j,k].
// ---------------------------------------------------------------------------
#define TI2 10
#define KB2_SMEM (NN * HH * 4 + TI2 * NN * 4)   // 55200 B

__global__ __launch_bounds__(128) void kB2(const float* __restrict__ lf) {
    extern __shared__ float sm2[];
    float* L_sh = sm2;               // [NN][HH]
    float* s_sh = sm2 + NN * HH;     // [TI2][NN]

    const int b   = blockIdx.x / (NN / TI2);
    const int i0  = (blockIdx.x % (NN / TI2)) * TI2;
    const int tid = threadIdx.x;

    {
        const float4* Ls = (const float4*)(lf + (size_t)b * NN * HH);
        float4* Ld = (float4*)L_sh;
        for (int t = tid; t < NN * HH / 4; t += 128) Ld[t] = Ls[t];
        const float* As = d_ATT + (size_t)(b * NN + i0) * NN;
        for (int t = tid; t < TI2 * NN; t += 128) s_sh[t] = As[t];
    }
    __syncthreads();

    const int k = tid;
    float acc[TI2];
    #pragma unroll
    for (int ii = 0; ii < TI2; ++ii) acc[ii] = 0.f;

    #pragma unroll 2
    for (int j = 0; j < NN; ++j) {
        const float lv = L_sh[j * HH + k];
        #pragma unroll
        for (int ii = 0; ii < TI2; ++ii)
            acc[ii] = fmaf(s_sh[ii * NN + j], lv, acc[ii]);
    }
    #pragma unroll
    for (int ii = 0; ii < TI2; ++ii)
        d_G[(size_t)(b * NN + i0 + ii) * HH + k] = acc[ii];
}

// ---------------------------------------------------------------------------
// Kernel C: gather epilogue. 8 e per 256-thread block; each thread drives
// TWO e's (MLP 4 on the gathered L2 reads). Streaming stores.
// ---------------------------------------------------------------------------
__global__ __launch_bounds__(256) void kC(const float* __restrict__ lf,
                                          const int* __restrict__ idx,
                                          float* __restrict__ out) {
    const int e0   = blockIdx.x * 8 + (threadIdx.x >> 6);
    const int e1   = e0 + 4;
    const int half = (threadIdx.x >> 5) & 1;
    const int lane = threadIdx.x & 31;

    int b0 = idx[e0 * 3 + 0], i0 = idx[e0 * 3 + 1], j0 = idx[e0 * 3 + 2];
    int b1 = idx[e1 * 3 + 0], i1 = idx[e1 * 3 + 1], j1 = idx[e1 * 3 + 2];
    b0 = min(max(b0, 0), BB - 1); i0 = min(max(i0, 0), NN - 1); j0 = min(max(j0, 0), NN - 1);
    b1 = min(max(b1, 0), BB - 1); i1 = min(max(i1, 0), NN - 1); j1 = min(max(j1, 0), NN - 1);

    const size_t ri0 = ((size_t)b0 * NN + i0) * (HH / 4);
    const size_t rj0 = ((size_t)b0 * NN + j0) * (HH / 4);
    const size_t ri1 = ((size_t)b1 * NN + i1) * (HH / 4);
    const size_t rj1 = ((size_t)b1 * NN + j1) * (HH / 4);
    float4* o = (float4*)out;

    const float4* S = (half == 0) ? (const float4*)lf : (const float4*)d_G;
    const size_t obase = (half == 0) ? 0 : (size_t)EE * 32;

    const float4 a0 = __ldg(S + ri0 + lane), c0 = __ldg(S + rj0 + lane);
    const float4 a1 = __ldg(S + ri1 + lane), c1 = __ldg(S + rj1 + lane);

    float4 r0; r0.x = a0.x + c0.x; r0.y = a0.y + c0.y; r0.z = a0.z + c0.z; r0.w = a0.w + c0.w;
    float4 r1; r1.x = a1.x + c1.x; r1.y = a1.y + c1.y; r1.z = a1.z + c1.z; r1.w = a1.w + c1.w;
    __stcs(o + obase + (size_t)e0 * 32 + lane, r0);
    __stcs(o + obase + (size_t)e1 * 32 + lane, r1);
}

// ---------------------------------------------------------------------------
extern "C" void kernel_launch(void* const* d_in, const int* in_sizes, int n_in,
                              void* d_out, int out_size) {
    const float* lf   = (const float*)d_in[0];
    const float* bin  = (const float*)d_in[1];
    const int*   sidx = (const int*)d_in[2];
    const float* Wap  = (const float*)d_in[3];
    const float* Wb   = (const float*)d_in[4];
    const float* bb   = (const float*)d_in[5];
    const float* Watt = (const float*)d_in[6];
    const float* batt = (const float*)d_in[7];
    float*       out  = (float*)d_out;

    static bool attr_set = false;
    if (!attr_set) {
        cudaFuncSetAttribute(kB1m, cudaFuncAttributeMaxDynamicSharedMemorySize, KB1M_SMEM);
        cudaFuncSetAttribute(kB2,  cudaFuncAttributeMaxDynamicSharedMemorySize, KB2_SMEM);
        attr_set = true;
    }

    kA  <<<BB * NN / RA, 512>>>(lf, Wap, bb);
    kB1m<<<BB * (NN / TIM), 256, KB1M_SMEM>>>(bin, Wb, Watt, batt);
    kB2 <<<BB * (NN / TI2), 128, KB2_SMEM>>>(lf);
    kC  <<<EE / 8, 256>>>(lf, sidx, out);
}